// round 14
// baseline (speedup 1.0000x reference)
#include <cuda_runtime.h>
#include <cuda_bf16.h>
#include <math.h>
#include <stdint.h>

#define NN 10000
#define NE 160000

// ===================== device scratch =====================
__device__ __nv_bfloat16 g_zh[(size_t)NE*128], g_zl[(size_t)NE*128];
__device__ __nv_bfloat16 g_xh[(size_t)NE*192], g_xl[(size_t)NE*192];
__device__ __nv_bfloat16 g_yh[(size_t)NE*192], g_yl[(size_t)NE*192];
__device__ __nv_bfloat16 g_y2h[(size_t)NE*192], g_y2l[(size_t)NE*192];
__device__ __nv_bfloat16 g_fh[(size_t)NN*960], g_fl[(size_t)NN*960];
__device__ __nv_bfloat16 g_Wn_h[1152*384],  g_Wn_l[1152*384];
__device__ __nv_bfloat16 g_Wz_h[576*128],   g_Wz_l[576*128];
__device__ __nv_bfloat16 g_Ww2_h[192*192],  g_Ww2_l[192*192];
__device__ __nv_bfloat16 g_Wv2_h[192*192],  g_Wv2_l[192*192];
__device__ __nv_bfloat16 g_Wv3_h[192*192],  g_Wv3_l[192*192];
__device__ __nv_bfloat16 g_Wo_h[384*960],   g_Wo_l[384*960];
__device__ float g_bias_node[1152], g_bias_z[576];
__device__ float g_node[(size_t)NN*1152];
__device__ float g_qpts[NN*144], g_kpts[NN*144], g_vpts[NN*288];
__device__ float g_vdst[(size_t)NE*192];
__device__ float g_alog[NE*12], g_bed[NE*12], g_pair[NE*32];
__device__ int g_cnt[NN], g_off[NN+1], g_cur[NN], g_order[NE];

__device__ __forceinline__ void split2(float v, __nv_bfloat16& h, __nv_bfloat16& l){
    h = __float2bfloat16(v);
    l = __float2bfloat16(v - __bfloat162float(h));
}

// ===================== cp.async / ldmatrix / mma =====================
__device__ __forceinline__ void cpasync16(void* sptr, const void* gptr, bool pred){
    uint32_t sa = (uint32_t)__cvta_generic_to_shared(sptr);
    int sz = pred ? 16 : 0;
    asm volatile("cp.async.cg.shared.global [%0], [%1], 16, %2;" :: "r"(sa), "l"(gptr), "r"(sz));
}
#define CP_COMMIT() asm volatile("cp.async.commit_group;" ::: "memory")
#define CP_WAIT(n)  asm volatile("cp.async.wait_group %0;" :: "n"(n) : "memory")

__device__ __forceinline__ void ldm_x4(uint32_t* r, const __nv_bfloat16* p){
    uint32_t a = (uint32_t)__cvta_generic_to_shared(p);
    asm volatile("ldmatrix.sync.aligned.m8n8.x4.shared.b16 {%0,%1,%2,%3}, [%4];"
        : "=r"(r[0]), "=r"(r[1]), "=r"(r[2]), "=r"(r[3]) : "r"(a));
}
__device__ __forceinline__ void ldm_x2(uint32_t& r0, uint32_t& r1, const __nv_bfloat16* p){
    uint32_t a = (uint32_t)__cvta_generic_to_shared(p);
    asm volatile("ldmatrix.sync.aligned.m8n8.x2.shared.b16 {%0,%1}, [%2];"
        : "=r"(r0), "=r"(r1) : "r"(a));
}
__device__ __forceinline__ void mma_bf16(float* c, uint32_t a0, uint32_t a1,
                                         uint32_t a2, uint32_t a3,
                                         uint32_t b0, uint32_t b1){
    asm volatile(
        "mma.sync.aligned.m16n8k16.row.col.f32.bf16.bf16.f32 "
        "{%0,%1,%2,%3}, {%4,%5,%6,%7}, {%8,%9}, {%0,%1,%2,%3};"
        : "+f"(c[0]), "+f"(c[1]), "+f"(c[2]), "+f"(c[3])
        : "r"(a0), "r"(a1), "r"(a2), "r"(a3), "r"(b0), "r"(b1));
}

// ===================== conversion kernels =====================
__global__ void splitf4_kernel(const float4* __restrict__ src,
                               uint2* __restrict__ h, uint2* __restrict__ l,
                               size_t n4){
    size_t i = (size_t)blockIdx.x * blockDim.x + threadIdx.x;
    if (i >= n4) return;
    float4 v = src[i];
    __nv_bfloat16 h0,l0,h1,l1,h2,l2,h3,l3;
    split2(v.x,h0,l0); split2(v.y,h1,l1); split2(v.z,h2,l2); split2(v.w,h3,l3);
    __nv_bfloat162 ph0(h0,h1), ph1(h2,h3), pl0(l0,l1), pl1(l2,l3);
    uint2 uh, ul;
    uh.x = *reinterpret_cast<uint32_t*>(&ph0); uh.y = *reinterpret_cast<uint32_t*>(&ph1);
    ul.x = *reinterpret_cast<uint32_t*>(&pl0); ul.y = *reinterpret_cast<uint32_t*>(&pl1);
    h[i] = uh; l[i] = ul;
}
__global__ void wconv_kernel(const float* __restrict__ src, int N, int K, int ld,
                             __nv_bfloat16* __restrict__ dh, __nv_bfloat16* __restrict__ dl){
    int i = blockIdx.x * blockDim.x + threadIdx.x;
    if (i >= N*K) return;
    int n = i / K, k = i % K;
    __nv_bfloat16 a,b; split2(src[(size_t)k*ld + n], a, b);
    dh[i]=a; dl[i]=b;
}
__global__ void wnconv_kernel(const float* __restrict__ Wq, const float* __restrict__ Wkv,
                              const float* __restrict__ Ww1, const float* __restrict__ Wv1){
    int i = blockIdx.x * blockDim.x + threadIdx.x;
    if (i >= 1152*384) return;
    int n = i / 384, k = i % 384;
    float v;
    if (n < 144)      v = Wq[k*144 + n];
    else if (n < 576) v = Wkv[k*432 + (n-144)];
    else if (n < 768) v = Ww1[(size_t)k*192 + (n-576)];
    else if (n < 960) v = Ww1[(size_t)(384+k)*192 + (n-768)];
    else              v = Wv1[(size_t)k*192 + (n-960)];
    __nv_bfloat16 a,b; split2(v, a, b);
    g_Wn_h[i]=a; g_Wn_l[i]=b;
}
__global__ void wzcat_kernel(const float* __restrict__ Ww1z, const float* __restrict__ Wv1z,
                             const float* __restrict__ Wb, const float* __restrict__ Wdz){
    int i = blockIdx.x * blockDim.x + threadIdx.x;
    if (i >= 576*128) return;
    int n = i / 128, k = i % 128;
    float v;
    if (n < 192)      v = Ww1z[(size_t)k*192 + n];
    else if (n < 384) v = Wv1z[(size_t)k*192 + (n-192)];
    else if (n < 396) v = Wb[k*12 + (n-384)];
    else if (n < 428) v = Wdz[k*32 + (n-396)];
    else v = 0.f;
    __nv_bfloat16 a,b; split2(v, a, b);
    g_Wz_h[i]=a; g_Wz_l[i]=b;
}
__global__ void biascat_kernel(const float* __restrict__ bq, const float* __restrict__ bkv,
                               const float* __restrict__ bw1, const float* __restrict__ bv1,
                               const float* __restrict__ bb, const float* __restrict__ bdz){
    int i = blockIdx.x * blockDim.x + threadIdx.x;
    if (i < 1152) g_bias_node[i] = (i < 144) ? bq[i] : (i < 576) ? bkv[i-144] : 0.f;
    if (i < 576) {
        float v;
        if (i < 192)      v = bw1[i];
        else if (i < 384) v = bv1[i-192];
        else if (i < 396) v = bb[i-384];
        else if (i < 428) v = bdz[i-396];
        else v = 0.f;
        g_bias_z[i] = v;
    }
}

// ===================== HMMA GEMM (BM=128, BN=192, 512 thr, 16 warps) ========
// modes: 0 fp32 float2 store (ldo); 3 relu+split -> oh/ol (192);
//        4 relu + fused W3 -> atomicAdd into alog;  6 merged z epilogue
#define LDA 72
#define OFF_AH 0
#define OFF_AL (128*LDA)
#define OFF_BH (2*128*LDA)
#define OFF_BL (2*128*LDA + 192*LDA)
#define STAGE  (2*128*LDA + 2*192*LDA)     // 46080 elems = 92160 B
#define SMEM_BYTES (2*STAGE*2)             // 184320 B
#define S1LOG 0.041666666666666664f

__global__ void __launch_bounds__(512, 1) hmma_gemm(
    const __nv_bfloat16* __restrict__ Ah, const __nv_bfloat16* __restrict__ Al,
    const __nv_bfloat16* __restrict__ Bh, const __nv_bfloat16* __restrict__ Bl,
    const float* __restrict__ bias,
    int M, int K, int mode,
    const int* __restrict__ ei, const float* __restrict__ nodep,
    const float* __restrict__ W3,
    float* __restrict__ outF, int ldo,
    __nv_bfloat16* __restrict__ oh, __nv_bfloat16* __restrict__ ol,
    __nv_bfloat16* __restrict__ o2h, __nv_bfloat16* __restrict__ o2l,
    float* __restrict__ bedF, float* __restrict__ pairF)
{
    extern __shared__ __nv_bfloat16 sm[];
    __shared__ float sW3[192*12];
    const int tid = threadIdx.x;
    const int w = tid >> 5, lane = tid & 31;
    const int lr = lane >> 2;
    const int lc = (lane & 3) * 2;
    const int warp_m = w >> 2, warp_n = w & 3;        // 4x4 warp grid
    const int m_base = warp_m * 32, n_base = warp_n * 48;
    const int m0 = blockIdx.y * 128;
    const int n0 = blockIdx.x * 192;
    const int nk = K >> 6;

    const int l_row = tid >> 3;        // 0..63
    const int l_k16 = tid & 7;

    const int aoffb = (m_base + (lane & 7) + ((lane >> 3) & 1)*8)*LDA + ((lane >> 4) & 1)*8;
    const int boffb = (n_base + (lane & 7))*LDA + ((lane >> 3) & 1)*8;

    if (mode == 4)
        for (int i = tid; i < 192*12; i += 512) sW3[i] = W3[i];

    float acc[2][6][4];
#pragma unroll
    for (int mt = 0; mt < 2; mt++)
#pragma unroll
        for (int nt = 0; nt < 6; nt++)
#pragma unroll
            for (int q = 0; q < 4; q++) acc[mt][nt][q] = 0.f;

    auto load_tile = [&](int c, int stg){
        const int c64 = c << 6;
        __nv_bfloat16* base = sm + stg*STAGE;
#pragma unroll
        for (int r = 0; r < 2; r++) {
            int row = l_row + r*64;
            int grow = m0 + row;
            bool p = (grow < M);
            size_t off = (size_t)grow * K + c64 + l_k16*8;
            cpasync16(base + OFF_AH + row*LDA + l_k16*8, Ah + (p ? off : 0), p);
            cpasync16(base + OFF_AL + row*LDA + l_k16*8, Al + (p ? off : 0), p);
        }
#pragma unroll
        for (int r = 0; r < 3; r++) {
            int row = l_row + r*64;
            size_t off = (size_t)(n0 + row) * K + c64 + l_k16*8;
            cpasync16(base + OFF_BH + row*LDA + l_k16*8, Bh + off, true);
            cpasync16(base + OFF_BL + row*LDA + l_k16*8, Bl + off, true);
        }
    };

    load_tile(0, 0);
    CP_COMMIT();

    for (int c = 0; c < nk; ++c) {
        if (c + 1 < nk) { load_tile(c+1, (c+1)&1); CP_COMMIT(); CP_WAIT(1); }
        else CP_WAIT(0);
        __syncthreads();

        const __nv_bfloat16* base = sm + (c&1)*STAGE;
        const __nv_bfloat16* sAh = base + OFF_AH;
        const __nv_bfloat16* sAl = base + OFF_AL;
        const __nv_bfloat16* sBh = base + OFF_BH;
        const __nv_bfloat16* sBl = base + OFF_BL;

#pragma unroll
        for (int kk = 0; kk < 4; ++kk) {
            uint32_t ah[2][4], al_[2][4];
            uint32_t bh[6][2], bl[6][2];
#pragma unroll
            for (int mt = 0; mt < 2; mt++) {
                ldm_x4(ah[mt],  sAh + aoffb + mt*16*LDA + kk*16);
                ldm_x4(al_[mt], sAl + aoffb + mt*16*LDA + kk*16);
            }
#pragma unroll
            for (int nt = 0; nt < 6; nt++) {
                ldm_x2(bh[nt][0], bh[nt][1], sBh + boffb + nt*8*LDA + kk*16);
                ldm_x2(bl[nt][0], bl[nt][1], sBl + boffb + nt*8*LDA + kk*16);
            }
#pragma unroll
            for (int nt = 0; nt < 6; nt++)
#pragma unroll
                for (int mt = 0; mt < 2; mt++)
                    mma_bf16(acc[mt][nt], ah[mt][0], ah[mt][1], ah[mt][2], ah[mt][3],
                             bh[nt][0], bh[nt][1]);
#pragma unroll
            for (int nt = 0; nt < 6; nt++)
#pragma unroll
                for (int mt = 0; mt < 2; mt++)
                    mma_bf16(acc[mt][nt], ah[mt][0], ah[mt][1], ah[mt][2], ah[mt][3],
                             bl[nt][0], bl[nt][1]);
#pragma unroll
            for (int nt = 0; nt < 6; nt++)
#pragma unroll
                for (int mt = 0; mt < 2; mt++)
                    mma_bf16(acc[mt][nt], al_[mt][0], al_[mt][1], al_[mt][2], al_[mt][3],
                             bh[nt][0], bh[nt][1]);
        }
        __syncthreads();
    }

    // ---------------- epilogue ----------------
    if (mode == 4) {
#pragma unroll
        for (int mt = 0; mt < 2; mt++) {
#pragma unroll
            for (int half = 0; half < 2; half++) {
                int grow = m0 + m_base + mt*16 + lr + half*8;
                float a12[12];
#pragma unroll
                for (int q = 0; q < 12; q++) a12[q] = 0.f;
#pragma unroll
                for (int nt = 0; nt < 6; nt++) {
                    int gcol = n0 + n_base + nt*8 + lc;
                    float v0 = fmaxf(acc[mt][nt][half*2 + 0] + bias[gcol], 0.f);
                    float v1 = fmaxf(acc[mt][nt][half*2 + 1] + bias[gcol+1], 0.f);
#pragma unroll
                    for (int q = 0; q < 12; q++)
                        a12[q] += v0 * sW3[gcol*12 + q] + v1 * sW3[(gcol+1)*12 + q];
                }
#pragma unroll
                for (int q = 0; q < 12; q++) {
                    a12[q] += __shfl_xor_sync(0xFFFFFFFFu, a12[q], 1);
                    a12[q] += __shfl_xor_sync(0xFFFFFFFFu, a12[q], 2);
                }
                if ((lane & 3) == 0) {
#pragma unroll
                    for (int q = 0; q < 12; q++)
                        atomicAdd(outF + (size_t)grow*12 + q, a12[q] * S1LOG);
                }
            }
        }
        return;
    }
#pragma unroll
    for (int mt = 0; mt < 2; mt++) {
#pragma unroll
        for (int half = 0; half < 2; half++) {
            int grow = m0 + m_base + mt*16 + lr + half*8;
            if (grow >= M) continue;
            int esrc = 0, edst = 0;
            if (mode == 6) { esrc = ei[NE + grow]; edst = ei[grow]; }
#pragma unroll
            for (int nt = 0; nt < 6; nt++) {
                int gcol = n0 + n_base + nt*8 + lc;
                float v0 = acc[mt][nt][half*2 + 0] + bias[gcol];
                float v1 = acc[mt][nt][half*2 + 1] + bias[gcol+1];
                if (mode == 0) {
                    *reinterpret_cast<float2*>(outF + (size_t)grow*ldo + gcol) =
                        make_float2(v0, v1);
                } else if (mode == 3) {
                    v0 = fmaxf(v0, 0.f); v1 = fmaxf(v1, 0.f);
                    __nv_bfloat16 h0,l0,h1,l1;
                    split2(v0,h0,l0); split2(v1,h1,l1);
                    *reinterpret_cast<__nv_bfloat162*>(oh + (size_t)grow*192 + gcol) =
                        __nv_bfloat162(h0, h1);
                    *reinterpret_cast<__nv_bfloat162*>(ol + (size_t)grow*192 + gcol) =
                        __nv_bfloat162(l0, l1);
                } else { // mode 6
                    if (gcol < 192) {
                        float2 ga = *reinterpret_cast<const float2*>(nodep + (size_t)esrc*1152 + 576 + gcol);
                        float2 gb = *reinterpret_cast<const float2*>(nodep + (size_t)edst*1152 + 768 + gcol);
                        v0 = fmaxf(v0 + ga.x + gb.x, 0.f);
                        v1 = fmaxf(v1 + ga.y + gb.y, 0.f);
                        __nv_bfloat16 h0,l0,h1,l1;
                        split2(v0,h0,l0); split2(v1,h1,l1);
                        *reinterpret_cast<__nv_bfloat162*>(oh + (size_t)grow*192 + gcol) =
                            __nv_bfloat162(h0, h1);
                        *reinterpret_cast<__nv_bfloat162*>(ol + (size_t)grow*192 + gcol) =
                            __nv_bfloat162(l0, l1);
                    } else if (gcol < 384) {
                        int cc = gcol - 192;
                        float2 ga = *reinterpret_cast<const float2*>(nodep + (size_t)edst*1152 + 960 + cc);
                        v0 = fmaxf(v0 + ga.x, 0.f);
                        v1 = fmaxf(v1 + ga.y, 0.f);
                        __nv_bfloat16 h0,l0,h1,l1;
                        split2(v0,h0,l0); split2(v1,h1,l1);
                        *reinterpret_cast<__nv_bfloat162*>(o2h + (size_t)grow*192 + cc) =
                            __nv_bfloat162(h0, h1);
                        *reinterpret_cast<__nv_bfloat162*>(o2l + (size_t)grow*192 + cc) =
                            __nv_bfloat162(l0, l1);
                    } else if (gcol < 396) {
                        bedF[(size_t)grow*12 + (gcol-384)] = v0;
                        bedF[(size_t)grow*12 + (gcol-383)] = v1;
                    } else if (gcol < 428) {
                        *reinterpret_cast<float2*>(pairF + (size_t)grow*32 + (gcol-396)) =
                            make_float2(v0, v1);
                    }
                }
            }
        }
    }
}

// ===================== point transforms =====================
__global__ void points_kernel(const float* __restrict__ rots, const float* __restrict__ trans){
    int idx = blockIdx.x * blockDim.x + threadIdx.x;
    if (idx >= NN * 192) return;
    int node = idx / 192;
    int p = idx % 192;
    const float* R = rots + node*9;
    float t0 = 0.1f*trans[node*3+0], t1 = 0.1f*trans[node*3+1], t2 = 0.1f*trans[node*3+2];
    if (p < 48) {
        const float* f = g_node + (size_t)node*1152;
        float l0=f[p], l1=f[48+p], l2=f[96+p];
        float g0=R[0]*l0+R[1]*l1+R[2]*l2+t0;
        float g1=R[3]*l0+R[4]*l1+R[5]*l2+t1;
        float g2=R[6]*l0+R[7]*l1+R[8]*l2+t2;
        float* o = g_qpts + (size_t)node*144 + p*3;
        o[0]=g0; o[1]=g1; o[2]=g2;
    } else {
        int q = p - 48;
        const float* f = g_node + (size_t)node*1152 + 144;
        float l0=f[q], l1=f[144+q], l2=f[288+q];
        float g0=R[0]*l0+R[1]*l1+R[2]*l2+t0;
        float g1=R[3]*l0+R[4]*l1+R[5]*l2+t1;
        float g2=R[6]*l0+R[7]*l1+R[8]*l2+t2;
        int h = q/12, ii = q%12;
        if (ii < 4) { float* o = g_kpts + (size_t)node*144 + (h*4+ii)*3; o[0]=g0;o[1]=g1;o[2]=g2; }
        else        { float* o = g_vpts + (size_t)node*288 + (h*8+(ii-4))*3; o[0]=g0;o[1]=g1;o[2]=g2; }
    }
}

// ===================== logit init =====================
__global__ void init_logit_kernel(
    const int* __restrict__ ei, const float* __restrict__ mask,
    const float* __restrict__ hw, const float* __restrict__ b3)
{
    int idx = blockIdx.x * blockDim.x + threadIdx.x;
    if (idx >= NE * 12) return;
    int e = idx / 12, h = idx % 12;
    int src = ei[NE + e], dst = ei[e];
    float hv = hw[h];
    float sp = (hv > 20.f) ? hv : log1pf(expf(hv));
    float hw_sp = sp * 0.13608276348795434f;
    const float* qp = g_qpts + (size_t)src*144 + h*12;
    const float* kp = g_kpts + (size_t)dst*144 + h*12;
    float pt = 0.f;
#pragma unroll
    for (int j = 0; j < 12; ++j) { float d = qp[j] - kp[j]; pt += d*d; }
    pt *= hw_sp * -0.5f;
    float em = 100000.0f * (mask[dst]*mask[src] - 1.0f);
    g_alog[idx] = b3[h] * S1LOG + 0.5773502691896258f * g_bed[idx] + pt + em;
}

// ===================== CSR =====================
__global__ void zero_cnt_kernel(){ int i = blockIdx.x*blockDim.x+threadIdx.x; if (i<NN) g_cnt[i]=0; }
__global__ void count_kernel(const int* __restrict__ ei){
    int e = blockIdx.x*blockDim.x+threadIdx.x;
    if (e < NE) atomicAdd(&g_cnt[ei[NE+e]], 1);
}
__global__ void scan_kernel(){
    __shared__ int ps[1024];
    int t = threadIdx.x;
    const int per = (NN + 1023)/1024;
    int s = 0;
    for (int i = 0; i < per; i++){ int id = t*per+i; if (id < NN) s += g_cnt[id]; }
    ps[t] = s;
    for (int off = 1; off < 1024; off <<= 1){
        __syncthreads();
        int v = (t >= off) ? ps[t-off] : 0;
        __syncthreads();
        ps[t] += v;
    }
    __syncthreads();
    int base = (t > 0) ? ps[t-1] : 0;
    for (int i = 0; i < per; i++){
        int id = t*per+i;
        if (id < NN){ g_off[id]=base; g_cur[id]=base; base += g_cnt[id]; }
    }
    if (t == 1023) g_off[NN] = ps[1023];
}
__global__ void scatter_kernel(const int* __restrict__ ei){
    int e = blockIdx.x*blockDim.x+threadIdx.x;
    if (e < NE){ int pos = atomicAdd(&g_cur[ei[NE+e]], 1); g_order[pos] = e; }
}

// ===================== aggregation: 2 edges per barrier round ===============
__global__ void __launch_bounds__(256) aggregate_kernel(
    const int* __restrict__ ei, const float* __restrict__ rots, const float* __restrict__ trans)
{
    int n = blockIdx.x;
    int t = threadIdx.x;
    int beg = g_off[n], end = g_off[n+1];
    __shared__ float sm_max[12], sm_ex0[12], sm_ex1[12];
    __shared__ int sm_dst0, sm_dst1;
    __shared__ float sm_acc[876], R[9], tt[3];

    if (t < 12){
        float m = -3.4e38f;
        for (int j = beg; j < end; j++){ int e = g_order[j]; m = fmaxf(m, g_alog[e*12+t]); }
        sm_max[t] = m;
    }
    if (t < 9) R[t] = rots[n*9+t];
    if (t >= 16 && t < 19) tt[t-16] = 0.1f * trans[n*3 + (t-16)];
    __syncthreads();

    float racc[4] = {0.f,0.f,0.f,0.f};
    for (int j = beg; j < end; j += 2){
        int e0 = g_order[j];
        bool has1 = (j + 1 < end);
        int e1 = has1 ? g_order[j+1] : e0;
        if (t < 12){
            sm_ex0[t] = expf(g_alog[e0*12+t] - sm_max[t]);
            sm_ex1[t] = has1 ? expf(g_alog[e1*12+t] - sm_max[t]) : 0.f;
        }
        if (t == 12) sm_dst0 = ei[e0];
        if (t == 13) sm_dst1 = ei[e1];
        __syncthreads();
        int d0 = sm_dst0, d1 = sm_dst1;
#pragma unroll
        for (int r = 0; r < 4; r++){
            int idx = t + r*256;
            if (idx < 876){
                float c;
                if (idx < 192){
                    int h = idx >> 4;
                    c = sm_ex0[h] * g_vdst[(size_t)e0*192 + idx]
                      + sm_ex1[h] * g_vdst[(size_t)e1*192 + idx];
                } else if (idx < 480){
                    int r2 = idx-192; int h = r2/24;
                    c = sm_ex0[h] * g_vpts[(size_t)d0*288 + r2]
                      + sm_ex1[h] * g_vpts[(size_t)d1*288 + r2];
                } else if (idx < 864){
                    int r2 = idx-480; int h = r2 >> 5;
                    c = sm_ex0[h] * g_pair[(size_t)e0*32 + (r2&31)]
                      + sm_ex1[h] * g_pair[(size_t)e1*32 + (r2&31)];
                } else {
                    c = sm_ex0[idx-864] + sm_ex1[idx-864];
                }
                racc[r] += c;
            }
        }
        __syncthreads();
    }
#pragma unroll
    for (int r = 0; r < 4; r++){ int idx = t + r*256; if (idx < 876) sm_acc[idx] = racc[r]; }
    __syncthreads();

    __nv_bfloat16* fh = g_fh + (size_t)n*960;
    __nv_bfloat16* fl = g_fl + (size_t)n*960;
    auto put = [&](int i, float v){
        __nv_bfloat16 h,l; split2(v,h,l); fh[i]=h; fl[i]=l;
    };
    for (int task = t; task < 672; task += 256){
        if (task < 192){
            int h = task >> 4;
            put(task, sm_acc[task] / (sm_acc[864+h] + 1e-16f));
        } else if (task < 288){
            int hp = task - 192;
            int h = hp >> 3;
            float d = sm_acc[864+h] + 1e-16f;
            float vx = sm_acc[192+hp*3+0]/d - tt[0];
            float vy = sm_acc[192+hp*3+1]/d - tt[1];
            float vz = sm_acc[192+hp*3+2]/d - tt[2];
            float lx = R[0]*vx + R[3]*vy + R[6]*vz;
            float ly = R[1]*vx + R[4]*vy + R[7]*vz;
            float lz = R[2]*vx + R[5]*vy + R[8]*vz;
            put(192+hp, lx); put(288+hp, ly); put(384+hp, lz);
            put(480+hp, sqrtf(lx*lx+ly*ly+lz*lz+1e-8f));
        } else {
            int idx = task - 288;
            int h = idx >> 5;
            put(576+idx, sm_acc[480+idx] / (sm_acc[864+h] + 1e-16f));
        }
    }
}

// ===================== host =====================
template <typename T, typename S>
static T* sym(const S& s){ void* p=nullptr; cudaGetSymbolAddress(&p, s); return (T*)p; }

extern "C" void kernel_launch(void* const* d_in, const int* in_sizes, int n_in,
                              void* d_out, int out_size)
{
    const float* s    = (const float*)d_in[0];
    const float* z    = (const float*)d_in[1];
    const int*   ei   = (const int*)d_in[2];
    const float* rots = (const float*)d_in[3];
    const float* trans= (const float*)d_in[4];
    const float* mask = (const float*)d_in[5];
    const float* Ww1  = (const float*)d_in[6];
    const float* bw1  = (const float*)d_in[7];
    const float* Ww2  = (const float*)d_in[8];
    const float* bw2  = (const float*)d_in[9];
    const float* Ww3  = (const float*)d_in[10];
    const float* bw3  = (const float*)d_in[11];
    const float* Wv1  = (const float*)d_in[12];
    const float* bv1  = (const float*)d_in[13];
    const float* Wv2  = (const float*)d_in[14];
    const float* bv2  = (const float*)d_in[15];
    const float* Wv3  = (const float*)d_in[16];
    const float* bv3  = (const float*)d_in[17];
    const float* Wq   = (const float*)d_in[18];
    const float* bq   = (const float*)d_in[19];
    const float* Wkv  = (const float*)d_in[20];
    const float* bkv  = (const float*)d_in[21];
    const float* Wb   = (const float*)d_in[22];
    const float* bb   = (const float*)d_in[23];
    const float* Wdz  = (const float*)d_in[24];
    const float* bdz  = (const float*)d_in[25];
    const float* Wo   = (const float*)d_in[26];
    const float* bo   = (const float*)d_in[27];
    const float* hw   = (const float*)d_in[28];
    float* out = (float*)d_out;

    cudaFuncSetAttribute(hmma_gemm, cudaFuncAttributeMaxDynamicSharedMemorySize, SMEM_BYTES);

    __nv_bfloat16 *zh=sym<__nv_bfloat16>(g_zh), *zl=sym<__nv_bfloat16>(g_zl);
    __nv_bfloat16 *xh=sym<__nv_bfloat16>(g_xh), *xl=sym<__nv_bfloat16>(g_xl);
    __nv_bfloat16 *yh=sym<__nv_bfloat16>(g_yh), *yl=sym<__nv_bfloat16>(g_yl);
    __nv_bfloat16 *y2h=sym<__nv_bfloat16>(g_y2h), *y2l=sym<__nv_bfloat16>(g_y2l);
    __nv_bfloat16 *fh=sym<__nv_bfloat16>(g_fh), *fl=sym<__nv_bfloat16>(g_fl);
    __nv_bfloat16 *Wnh=sym<__nv_bfloat16>(g_Wn_h),  *Wnl=sym<__nv_bfloat16>(g_Wn_l);
    __nv_bfloat16 *Wzh=sym<__nv_bfloat16>(g_Wz_h),  *Wzl=sym<__nv_bfloat16>(g_Wz_l);
    __nv_bfloat16 *W2h=sym<__nv_bfloat16>(g_Ww2_h), *W2l=sym<__nv_bfloat16>(g_Ww2_l);
    __nv_bfloat16 *V2h=sym<__nv_bfloat16>(g_Wv2_h), *V2l=sym<__nv_bfloat16>(g_Wv2_l);
    __nv_bfloat16 *V3h=sym<__nv_bfloat16>(g_Wv3_h), *V3l=sym<__nv_bfloat16>(g_Wv3_l);
    __nv_bfloat16 *Woh=sym<__nv_bfloat16>(g_Wo_h),  *Wol=sym<__nv_bfloat16>(g_Wo_l);
    float* biasN = sym<float>(g_bias_node);
    float* biasZ = sym<float>(g_bias_z);
    float* node  = sym<float>(g_node);
    float* vdst  = sym<float>(g_vdst);
    float* alog  = sym<float>(g_alog);
    float* bed   = sym<float>(g_bed);
    float* pair  = sym<float>(g_pair);

    auto tcg = [&](const __nv_bfloat16* Ah_, const __nv_bfloat16* Al_,
                   const __nv_bfloat16* Bh_, const __nv_bfloat16* Bl_,
                   const float* bias_, int M_, int K_, int Ntot_, int mode_,
                   const float* W3_,
                   float* outF_, int ldo_,
                   __nv_bfloat16* oh_, __nv_bfloat16* ol_,
                   __nv_bfloat16* o2h_, __nv_bfloat16* o2l_,
                   float* bedF_, float* pairF_){
        dim3 grid(Ntot_/192, (M_+127)/128);
        hmma_gemm<<<grid, 512, SMEM_BYTES>>>(Ah_, Al_, Bh_, Bl_, bias_, M_, K_, mode_,
                                             ei, node, W3_, outF_, ldo_, oh_, ol_,
                                             o2h_, o2l_, bedF_, pairF_);
    };

    wnconv_kernel<<<(1152*384+255)/256, 256>>>(Wq, Wkv, Ww1, Wv1);
    wzcat_kernel<<<(576*128+255)/256, 256>>>(Ww1 + 768*192, Wv1 + 384*192, Wb, Wdz);
    biascat_kernel<<<(1152+255)/256, 256>>>(bq, bkv, bw1, bv1, bb, bdz);
    splitf4_kernel<<<(unsigned)(((size_t)NE*128/4 + 255)/256), 256>>>(
        (const float4*)z, (uint2*)zh, (uint2*)zl, (size_t)NE*128/4);
    splitf4_kernel<<<(unsigned)(((size_t)NN*384/4 + 255)/256), 256>>>(
        (const float4*)s, (uint2*)fh, (uint2*)fl, (size_t)NN*384/4);

    // node projections  [NN x 1152] = s @ [Wq|Wkv|Ww1s|Ww1d|Wv1d]
    tcg(fh, fl, Wnh, Wnl, biasN, NN, 384, 1152, 0, 0, node, 1152, 0,0,0,0,0,0);
    points_kernel<<<(NN*192+255)/256, 256>>>(rots, trans);

    // remaining weight conversions
    wconv_kernel<<<(192*192+255)/256, 256>>>(Ww2, 192, 192, 192, W2h, W2l);
    wconv_kernel<<<(192*192+255)/256, 256>>>(Wv2, 192, 192, 192, V2h, V2l);
    wconv_kernel<<<(192*192+255)/256, 256>>>(Wv3, 192, 192, 192, V3h, V3l);
    wconv_kernel<<<(384*960+255)/256, 256>>>(Wo, 384, 960, 384, Woh, Wol);

    // merged z GEMM (Ntot padded to 576): x, y, bed, pair
    tcg(zh, zl, Wzh, Wzl, biasZ, NE, 128, 576, 6, 0, 0, 0, xh, xl, yh, yl, bed, pair);

    // init logits, then W2 GEMM with fused W3 -> atomicAdd alog
    init_logit_kernel<<<(NE*12+255)/256, 256>>>(ei, mask, hw, bw3);
    tcg(xh, xl, W2h, W2l, bw2, NE, 192, 192, 4, Ww3, alog, 0, 0,0,0,0,0,0);

    // value chain: y -> y2 -> vdst
    tcg(yh, yl, V2h, V2l, bv2, NE, 192, 192, 3, 0, 0, 0, y2h, y2l, 0,0,0,0);
    tcg(y2h, y2l, V3h, V3l, bv3, NE, 192, 192, 0, 0, vdst, 192, 0,0,0,0,0,0);

    // CSR
    zero_cnt_kernel<<<(NN+255)/256, 256>>>();
    count_kernel<<<(NE+255)/256, 256>>>(ei);
    scan_kernel<<<1, 1024>>>();
    scatter_kernel<<<(NE+255)/256, 256>>>(ei);

    // softmax + aggregation (writes split feats into fh/fl)
    aggregate_kernel<<<NN, 256>>>(ei, rots, trans);

    // output projection
    tcg(fh, fl, Woh, Wol, bo, NN, 960, 384, 0, 0, out, 384, 0,0,0,0,0,0);
}

// round 17
// speedup vs baseline: 1.1077x; 1.1077x over previous
#include <cuda_runtime.h>
#include <cuda_bf16.h>
#include <math.h>
#include <stdint.h>

#define NN 10000
#define NE 160000

// ===================== device scratch =====================
__device__ __nv_bfloat16 g_zh[(size_t)NE*128], g_zl[(size_t)NE*128];
__device__ __nv_bfloat16 g_xh[(size_t)NE*192], g_xl[(size_t)NE*192];
__device__ __nv_bfloat16 g_yh[(size_t)NE*192], g_yl[(size_t)NE*192];
__device__ __nv_bfloat16 g_y2h[(size_t)NE*192], g_y2l[(size_t)NE*192];
__device__ __nv_bfloat16 g_fh[(size_t)NN*960], g_fl[(size_t)NN*960];
__device__ __nv_bfloat16 g_Wn_h[1152*384],  g_Wn_l[1152*384];
__device__ __nv_bfloat16 g_Wz_h[480*128],   g_Wz_l[480*128];
__device__ __nv_bfloat16 g_Ww2_h[192*192],  g_Ww2_l[192*192];
__device__ __nv_bfloat16 g_Wv2_h[192*192],  g_Wv2_l[192*192];
__device__ __nv_bfloat16 g_Wv3_h[192*192],  g_Wv3_l[192*192];
__device__ __nv_bfloat16 g_Wo_h[384*960],   g_Wo_l[384*960];
__device__ float g_bias_node[1152], g_bias_z[480];
__device__ float g_node[(size_t)NN*1152];
__device__ float g_qpts[NN*144], g_kpts[NN*144], g_vpts[NN*288];
__device__ float g_vdst[(size_t)NE*192];
__device__ float g_alog[NE*12], g_bed[NE*12], g_pair[NE*32];
__device__ int g_cnt[NN], g_off[NN+1], g_cur[NN], g_order[NE];

__device__ __forceinline__ void split2(float v, __nv_bfloat16& h, __nv_bfloat16& l){
    h = __float2bfloat16(v);
    l = __float2bfloat16(v - __bfloat162float(h));
}

// ===================== cp.async / ldmatrix / mma =====================
__device__ __forceinline__ void cpasync16(void* sptr, const void* gptr, bool pred){
    uint32_t sa = (uint32_t)__cvta_generic_to_shared(sptr);
    int sz = pred ? 16 : 0;
    asm volatile("cp.async.cg.shared.global [%0], [%1], 16, %2;" :: "r"(sa), "l"(gptr), "r"(sz));
}
#define CP_COMMIT() asm volatile("cp.async.commit_group;" ::: "memory")
#define CP_WAIT(n)  asm volatile("cp.async.wait_group %0;" :: "n"(n) : "memory")

__device__ __forceinline__ void ldm_x4(uint32_t* r, const __nv_bfloat16* p){
    uint32_t a = (uint32_t)__cvta_generic_to_shared(p);
    asm volatile("ldmatrix.sync.aligned.m8n8.x4.shared.b16 {%0,%1,%2,%3}, [%4];"
        : "=r"(r[0]), "=r"(r[1]), "=r"(r[2]), "=r"(r[3]) : "r"(a));
}
__device__ __forceinline__ void ldm_x2(uint32_t& r0, uint32_t& r1, const __nv_bfloat16* p){
    uint32_t a = (uint32_t)__cvta_generic_to_shared(p);
    asm volatile("ldmatrix.sync.aligned.m8n8.x2.shared.b16 {%0,%1}, [%2];"
        : "=r"(r0), "=r"(r1) : "r"(a));
}
__device__ __forceinline__ void mma_bf16(float* c, uint32_t a0, uint32_t a1,
                                         uint32_t a2, uint32_t a3,
                                         uint32_t b0, uint32_t b1){
    asm volatile(
        "mma.sync.aligned.m16n8k16.row.col.f32.bf16.bf16.f32 "
        "{%0,%1,%2,%3}, {%4,%5,%6,%7}, {%8,%9}, {%0,%1,%2,%3};"
        : "+f"(c[0]), "+f"(c[1]), "+f"(c[2]), "+f"(c[3])
        : "r"(a0), "r"(a1), "r"(a2), "r"(a3), "r"(b0), "r"(b1));
}

// ===================== conversion kernels =====================
__global__ void splitf4_kernel(const float4* __restrict__ src,
                               uint2* __restrict__ h, uint2* __restrict__ l,
                               size_t n4){
    size_t i = (size_t)blockIdx.x * blockDim.x + threadIdx.x;
    if (i >= n4) return;
    float4 v = src[i];
    __nv_bfloat16 h0,l0,h1,l1,h2,l2,h3,l3;
    split2(v.x,h0,l0); split2(v.y,h1,l1); split2(v.z,h2,l2); split2(v.w,h3,l3);
    __nv_bfloat162 ph0(h0,h1), ph1(h2,h3), pl0(l0,l1), pl1(l2,l3);
    uint2 uh, ul;
    uh.x = *reinterpret_cast<uint32_t*>(&ph0); uh.y = *reinterpret_cast<uint32_t*>(&ph1);
    ul.x = *reinterpret_cast<uint32_t*>(&pl0); ul.y = *reinterpret_cast<uint32_t*>(&pl1);
    h[i] = uh; l[i] = ul;
}
__global__ void wconv_kernel(const float* __restrict__ src, int N, int K, int ld,
                             __nv_bfloat16* __restrict__ dh, __nv_bfloat16* __restrict__ dl){
    int i = blockIdx.x * blockDim.x + threadIdx.x;
    if (i >= N*K) return;
    int n = i / K, k = i % K;
    __nv_bfloat16 a,b; split2(src[(size_t)k*ld + n], a, b);
    dh[i]=a; dl[i]=b;
}
__global__ void wnconv_kernel(const float* __restrict__ Wq, const float* __restrict__ Wkv,
                              const float* __restrict__ Ww1, const float* __restrict__ Wv1){
    int i = blockIdx.x * blockDim.x + threadIdx.x;
    if (i >= 1152*384) return;
    int n = i / 384, k = i % 384;
    float v;
    if (n < 144)      v = Wq[k*144 + n];
    else if (n < 576) v = Wkv[k*432 + (n-144)];
    else if (n < 768) v = Ww1[(size_t)k*192 + (n-576)];
    else if (n < 960) v = Ww1[(size_t)(384+k)*192 + (n-768)];
    else              v = Wv1[(size_t)k*192 + (n-960)];
    __nv_bfloat16 a,b; split2(v, a, b);
    g_Wn_h[i]=a; g_Wn_l[i]=b;
}
__global__ void wzcat_kernel(const float* __restrict__ Ww1z, const float* __restrict__ Wv1z,
                             const float* __restrict__ Wb, const float* __restrict__ Wdz){
    int i = blockIdx.x * blockDim.x + threadIdx.x;
    if (i >= 480*128) return;
    int n = i / 128, k = i % 128;
    float v;
    if (n < 192)      v = Ww1z[(size_t)k*192 + n];
    else if (n < 384) v = Wv1z[(size_t)k*192 + (n-192)];
    else if (n < 396) v = Wb[k*12 + (n-384)];
    else if (n < 428) v = Wdz[k*32 + (n-396)];
    else v = 0.f;
    __nv_bfloat16 a,b; split2(v, a, b);
    g_Wz_h[i]=a; g_Wz_l[i]=b;
}
__global__ void biascat_kernel(const float* __restrict__ bq, const float* __restrict__ bkv,
                               const float* __restrict__ bw1, const float* __restrict__ bv1,
                               const float* __restrict__ bb, const float* __restrict__ bdz){
    int i = blockIdx.x * blockDim.x + threadIdx.x;
    if (i < 1152) g_bias_node[i] = (i < 144) ? bq[i] : (i < 576) ? bkv[i-144] : 0.f;
    if (i < 480) {
        float v;
        if (i < 192)      v = bw1[i];
        else if (i < 384) v = bv1[i-192];
        else if (i < 396) v = bb[i-384];
        else if (i < 428) v = bdz[i-396];
        else v = 0.f;
        g_bias_z[i] = v;
    }
}

// ===================== HMMA GEMM (BM=128, BN=96, 256 thr) ==================
// modes: 0 fp32 float2 store (ldo); 3 relu+split -> oh/ol (192);
//        4 relu + fused W3 -> atomicAdd into alog;  6 merged z epilogue
#define LDA 72
#define OFF_AH 0
#define OFF_AL (128*LDA)
#define OFF_BH (2*128*LDA)
#define OFF_BL (2*128*LDA + 96*LDA)
#define STAGE  (2*128*LDA + 2*96*LDA)
#define SMEM_BYTES (2*STAGE*2)
#define S1LOG 0.041666666666666664f

__global__ void __launch_bounds__(256, 1) hmma_gemm(
    const __nv_bfloat16* __restrict__ Ah, const __nv_bfloat16* __restrict__ Al,
    const __nv_bfloat16* __restrict__ Bh, const __nv_bfloat16* __restrict__ Bl,
    const float* __restrict__ bias,
    int M, int K, int mode,
    const int* __restrict__ ei, const float* __restrict__ nodep,
    const float* __restrict__ W3,
    float* __restrict__ outF, int ldo,
    __nv_bfloat16* __restrict__ oh, __nv_bfloat16* __restrict__ ol,
    __nv_bfloat16* __restrict__ o2h, __nv_bfloat16* __restrict__ o2l,
    float* __restrict__ bedF, float* __restrict__ pairF)
{
    extern __shared__ __nv_bfloat16 sm[];
    __shared__ float sW3[192*12];
    const int tid = threadIdx.x;
    const int w = tid >> 5, lane = tid & 31;
    const int lr = lane >> 2;
    const int lc = (lane & 3) * 2;
    const int warp_m = w >> 1, warp_n = w & 1;
    const int m_base = warp_m * 32, n_base = warp_n * 48;
    const int m0 = blockIdx.y * 128;
    const int n0 = blockIdx.x * 96;
    const int nk = K >> 6;

    const int l_row = tid >> 3;
    const int l_k16 = tid & 7;

    const int aoffb = (m_base + (lane & 7) + ((lane >> 3) & 1)*8)*LDA + ((lane >> 4) & 1)*8;
    const int boffb = (n_base + (lane & 7))*LDA + ((lane >> 3) & 1)*8;

    if (mode == 4)
        for (int i = tid; i < 192*12; i += 256) sW3[i] = W3[i];

    float acc[2][6][4];
#pragma unroll
    for (int mt = 0; mt < 2; mt++)
#pragma unroll
        for (int nt = 0; nt < 6; nt++)
#pragma unroll
            for (int q = 0; q < 4; q++) acc[mt][nt][q] = 0.f;

    auto load_tile = [&](int c, int stg){
        const int c64 = c << 6;
        __nv_bfloat16* base = sm + stg*STAGE;
#pragma unroll
        for (int r = 0; r < 4; r++) {
            int row = l_row + r*32;
            int grow = m0 + row;
            bool p = (grow < M);
            size_t off = (size_t)grow * K + c64 + l_k16*8;
            cpasync16(base + OFF_AH + row*LDA + l_k16*8, Ah + (p ? off : 0), p);
            cpasync16(base + OFF_AL + row*LDA + l_k16*8, Al + (p ? off : 0), p);
        }
#pragma unroll
        for (int r = 0; r < 3; r++) {
            int row = l_row + r*32;
            size_t off = (size_t)(n0 + row) * K + c64 + l_k16*8;
            cpasync16(base + OFF_BH + row*LDA + l_k16*8, Bh + off, true);
            cpasync16(base + OFF_BL + row*LDA + l_k16*8, Bl + off, true);
        }
    };

    load_tile(0, 0);
    CP_COMMIT();

    for (int c = 0; c < nk; ++c) {
        if (c + 1 < nk) { load_tile(c+1, (c+1)&1); CP_COMMIT(); CP_WAIT(1); }
        else CP_WAIT(0);
        __syncthreads();

        const __nv_bfloat16* base = sm + (c&1)*STAGE;
        const __nv_bfloat16* sAh = base + OFF_AH;
        const __nv_bfloat16* sAl = base + OFF_AL;
        const __nv_bfloat16* sBh = base + OFF_BH;
        const __nv_bfloat16* sBl = base + OFF_BL;

#pragma unroll
        for (int kk = 0; kk < 4; ++kk) {
            uint32_t ah[2][4], al_[2][4];
            uint32_t bh[6][2], bl[6][2];
#pragma unroll
            for (int mt = 0; mt < 2; mt++) {
                ldm_x4(ah[mt],  sAh + aoffb + mt*16*LDA + kk*16);
                ldm_x4(al_[mt], sAl + aoffb + mt*16*LDA + kk*16);
            }
#pragma unroll
            for (int nt = 0; nt < 6; nt++) {
                ldm_x2(bh[nt][0], bh[nt][1], sBh + boffb + nt*8*LDA + kk*16);
                ldm_x2(bl[nt][0], bl[nt][1], sBl + boffb + nt*8*LDA + kk*16);
            }
#pragma unroll
            for (int nt = 0; nt < 6; nt++)
#pragma unroll
                for (int mt = 0; mt < 2; mt++)
                    mma_bf16(acc[mt][nt], ah[mt][0], ah[mt][1], ah[mt][2], ah[mt][3],
                             bh[nt][0], bh[nt][1]);
#pragma unroll
            for (int nt = 0; nt < 6; nt++)
#pragma unroll
                for (int mt = 0; mt < 2; mt++)
                    mma_bf16(acc[mt][nt], ah[mt][0], ah[mt][1], ah[mt][2], ah[mt][3],
                             bl[nt][0], bl[nt][1]);
#pragma unroll
            for (int nt = 0; nt < 6; nt++)
#pragma unroll
                for (int mt = 0; mt < 2; mt++)
                    mma_bf16(acc[mt][nt], al_[mt][0], al_[mt][1], al_[mt][2], al_[mt][3],
                             bh[nt][0], bh[nt][1]);
        }
        __syncthreads();
    }

    // ---------------- epilogue ----------------
    if (mode == 4) {
#pragma unroll
        for (int mt = 0; mt < 2; mt++) {
#pragma unroll
            for (int half = 0; half < 2; half++) {
                int grow = m0 + m_base + mt*16 + lr + half*8;
                float a12[12];
#pragma unroll
                for (int q = 0; q < 12; q++) a12[q] = 0.f;
#pragma unroll
                for (int nt = 0; nt < 6; nt++) {
                    int gcol = n0 + n_base + nt*8 + lc;
                    float v0 = fmaxf(acc[mt][nt][half*2 + 0] + bias[gcol], 0.f);
                    float v1 = fmaxf(acc[mt][nt][half*2 + 1] + bias[gcol+1], 0.f);
#pragma unroll
                    for (int q = 0; q < 12; q++)
                        a12[q] += v0 * sW3[gcol*12 + q] + v1 * sW3[(gcol+1)*12 + q];
                }
#pragma unroll
                for (int q = 0; q < 12; q++) {
                    a12[q] += __shfl_xor_sync(0xFFFFFFFFu, a12[q], 1);
                    a12[q] += __shfl_xor_sync(0xFFFFFFFFu, a12[q], 2);
                }
                if ((lane & 3) == 0) {
#pragma unroll
                    for (int q = 0; q < 12; q++)
                        atomicAdd(outF + (size_t)grow*12 + q, a12[q] * S1LOG);
                }
            }
        }
        return;
    }
#pragma unroll
    for (int mt = 0; mt < 2; mt++) {
#pragma unroll
        for (int half = 0; half < 2; half++) {
            int grow = m0 + m_base + mt*16 + lr + half*8;
            if (grow >= M) continue;
            int esrc = 0, edst = 0;
            if (mode == 6) { esrc = ei[NE + grow]; edst = ei[grow]; }
#pragma unroll
            for (int nt = 0; nt < 6; nt++) {
                int gcol = n0 + n_base + nt*8 + lc;
                float v0 = acc[mt][nt][half*2 + 0] + bias[gcol];
                float v1 = acc[mt][nt][half*2 + 1] + bias[gcol+1];
                if (mode == 0) {
                    *reinterpret_cast<float2*>(outF + (size_t)grow*ldo + gcol) =
                        make_float2(v0, v1);
                } else if (mode == 3) {
                    v0 = fmaxf(v0, 0.f); v1 = fmaxf(v1, 0.f);
                    __nv_bfloat16 h0,l0,h1,l1;
                    split2(v0,h0,l0); split2(v1,h1,l1);
                    *reinterpret_cast<__nv_bfloat162*>(oh + (size_t)grow*192 + gcol) =
                        __nv_bfloat162(h0, h1);
                    *reinterpret_cast<__nv_bfloat162*>(ol + (size_t)grow*192 + gcol) =
                        __nv_bfloat162(l0, l1);
                } else { // mode 6
                    if (gcol < 192) {
                        float2 ga = *reinterpret_cast<const float2*>(nodep + (size_t)esrc*1152 + 576 + gcol);
                        float2 gb = *reinterpret_cast<const float2*>(nodep + (size_t)edst*1152 + 768 + gcol);
                        v0 = fmaxf(v0 + ga.x + gb.x, 0.f);
                        v1 = fmaxf(v1 + ga.y + gb.y, 0.f);
                        __nv_bfloat16 h0,l0,h1,l1;
                        split2(v0,h0,l0); split2(v1,h1,l1);
                        *reinterpret_cast<__nv_bfloat162*>(oh + (size_t)grow*192 + gcol) =
                            __nv_bfloat162(h0, h1);
                        *reinterpret_cast<__nv_bfloat162*>(ol + (size_t)grow*192 + gcol) =
                            __nv_bfloat162(l0, l1);
                    } else if (gcol < 384) {
                        int cc = gcol - 192;
                        float2 ga = *reinterpret_cast<const float2*>(nodep + (size_t)edst*1152 + 960 + cc);
                        v0 = fmaxf(v0 + ga.x, 0.f);
                        v1 = fmaxf(v1 + ga.y, 0.f);
                        __nv_bfloat16 h0,l0,h1,l1;
                        split2(v0,h0,l0); split2(v1,h1,l1);
                        *reinterpret_cast<__nv_bfloat162*>(o2h + (size_t)grow*192 + cc) =
                            __nv_bfloat162(h0, h1);
                        *reinterpret_cast<__nv_bfloat162*>(o2l + (size_t)grow*192 + cc) =
                            __nv_bfloat162(l0, l1);
                    } else if (gcol < 396) {
                        bedF[(size_t)grow*12 + (gcol-384)] = v0;
                        bedF[(size_t)grow*12 + (gcol-383)] = v1;
                    } else if (gcol < 428) {
                        *reinterpret_cast<float2*>(pairF + (size_t)grow*32 + (gcol-396)) =
                            make_float2(v0, v1);
                    }
                }
            }
        }
    }
}

// ===================== point transforms =====================
__global__ void points_kernel(const float* __restrict__ rots, const float* __restrict__ trans){
    int idx = blockIdx.x * blockDim.x + threadIdx.x;
    if (idx >= NN * 192) return;
    int node = idx / 192;
    int p = idx % 192;
    const float* R = rots + node*9;
    float t0 = 0.1f*trans[node*3+0], t1 = 0.1f*trans[node*3+1], t2 = 0.1f*trans[node*3+2];
    if (p < 48) {
        const float* f = g_node + (size_t)node*1152;
        float l0=f[p], l1=f[48+p], l2=f[96+p];
        float g0=R[0]*l0+R[1]*l1+R[2]*l2+t0;
        float g1=R[3]*l0+R[4]*l1+R[5]*l2+t1;
        float g2=R[6]*l0+R[7]*l1+R[8]*l2+t2;
        float* o = g_qpts + (size_t)node*144 + p*3;
        o[0]=g0; o[1]=g1; o[2]=g2;
    } else {
        int q = p - 48;
        const float* f = g_node + (size_t)node*1152 + 144;
        float l0=f[q], l1=f[144+q], l2=f[288+q];
        float g0=R[0]*l0+R[1]*l1+R[2]*l2+t0;
        float g1=R[3]*l0+R[4]*l1+R[5]*l2+t1;
        float g2=R[6]*l0+R[7]*l1+R[8]*l2+t2;
        int h = q/12, ii = q%12;
        if (ii < 4) { float* o = g_kpts + (size_t)node*144 + (h*4+ii)*3; o[0]=g0;o[1]=g1;o[2]=g2; }
        else        { float* o = g_vpts + (size_t)node*288 + (h*8+(ii-4))*3; o[0]=g0;o[1]=g1;o[2]=g2; }
    }
}

// ===================== logit init =====================
__global__ void init_logit_kernel(
    const int* __restrict__ ei, const float* __restrict__ mask,
    const float* __restrict__ hw, const float* __restrict__ b3)
{
    int idx = blockIdx.x * blockDim.x + threadIdx.x;
    if (idx >= NE * 12) return;
    int e = idx / 12, h = idx % 12;
    int src = ei[NE + e], dst = ei[e];
    float hv = hw[h];
    float sp = (hv > 20.f) ? hv : log1pf(expf(hv));
    float hw_sp = sp * 0.13608276348795434f;
    const float* qp = g_qpts + (size_t)src*144 + h*12;
    const float* kp = g_kpts + (size_t)dst*144 + h*12;
    float pt = 0.f;
#pragma unroll
    for (int j = 0; j < 12; ++j) { float d = qp[j] - kp[j]; pt += d*d; }
    pt *= hw_sp * -0.5f;
    float em = 100000.0f * (mask[dst]*mask[src] - 1.0f);
    g_alog[idx] = b3[h] * S1LOG + 0.5773502691896258f * g_bed[idx] + pt + em;
}

// ===================== CSR =====================
__global__ void zero_cnt_kernel(){ int i = blockIdx.x*blockDim.x+threadIdx.x; if (i<NN) g_cnt[i]=0; }
__global__ void count_kernel(const int* __restrict__ ei){
    int e = blockIdx.x*blockDim.x+threadIdx.x;
    if (e < NE) atomicAdd(&g_cnt[ei[NE+e]], 1);
}
__global__ void scan_kernel(){
    __shared__ int ps[1024];
    int t = threadIdx.x;
    const int per = (NN + 1023)/1024;
    int s = 0;
    for (int i = 0; i < per; i++){ int id = t*per+i; if (id < NN) s += g_cnt[id]; }
    ps[t] = s;
    for (int off = 1; off < 1024; off <<= 1){
        __syncthreads();
        int v = (t >= off) ? ps[t-off] : 0;
        __syncthreads();
        ps[t] += v;
    }
    __syncthreads();
    int base = (t > 0) ? ps[t-1] : 0;
    for (int i = 0; i < per; i++){
        int id = t*per+i;
        if (id < NN){ g_off[id]=base; g_cur[id]=base; base += g_cnt[id]; }
    }
    if (t == 1023) g_off[NN] = ps[1023];
}
__global__ void scatter_kernel(const int* __restrict__ ei){
    int e = blockIdx.x*blockDim.x+threadIdx.x;
    if (e < NE){ int pos = atomicAdd(&g_cur[ei[NE+e]], 1); g_order[pos] = e; }
}

// ===================== aggregation: parallel max + 4 edges per round ========
__global__ void __launch_bounds__(256) aggregate_kernel(
    const int* __restrict__ ei, const float* __restrict__ rots, const float* __restrict__ trans)
{
    int n = blockIdx.x;
    int t = threadIdx.x;
    int beg = g_off[n], end = g_off[n+1];
    __shared__ float sm_max[12];
    __shared__ float sm_pm[21][12];
    __shared__ float sm_ex[4][12];
    __shared__ int sm_e[4], sm_d[4];
    __shared__ float sm_acc[876], R[9], tt[3];

    // parallel max: 21 edge-groups x 12 heads (threads 0..251)
    if (t < 252){
        int g = t / 12, h = t - g*12;
        float m = -3.4e38f;
        for (int j = beg + g; j < end; j += 21)
            m = fmaxf(m, g_alog[g_order[j]*12 + h]);
        sm_pm[g][h] = m;
    }
    if (t < 9) R[t] = rots[n*9 + t];        // FIX: in-range threads
    if (t >= 32 && t < 35) tt[t-32] = 0.1f * trans[n*3 + (t-32)];
    __syncthreads();
    if (t < 12){
        float m = sm_pm[0][t];
#pragma unroll
        for (int g = 1; g < 21; g++) m = fmaxf(m, sm_pm[g][t]);
        sm_max[t] = m;
    }
    __syncthreads();

    float racc[4] = {0.f,0.f,0.f,0.f};
    for (int j = beg; j < end; j += 4){
        // 48 threads: q = t/12 (0..3), h = t%12
        if (t < 48){
            int q = t / 12, h = t - (t/12)*12;
            int jj = j + q;
            float ex = 0.f;
            if (jj < end){
                int e = g_order[jj];
                ex = expf(g_alog[e*12 + h] - sm_max[h]);
                if (h == 0) sm_e[q] = e;
            }
            sm_ex[q][h] = ex;
        }
        if (t >= 64 && t < 68){
            int q = t - 64;
            int jj = j + q;
            sm_d[q] = (jj < end) ? ei[g_order[jj]] : 0;
        }
        __syncthreads();
        int e0 = sm_e[0], e1 = (j+1<end)? sm_e[1] : e0;
        int e2 = (j+2<end)? sm_e[2] : e0, e3 = (j+3<end)? sm_e[3] : e0;
        int d0 = sm_d[0], d1 = (j+1<end)? sm_d[1] : d0;
        int d2 = (j+2<end)? sm_d[2] : d0, d3 = (j+3<end)? sm_d[3] : d0;
#pragma unroll
        for (int r = 0; r < 4; r++){
            int idx = t + r*256;
            if (idx < 876){
                float c;
                if (idx < 192){
                    int h = idx >> 4;
                    c = sm_ex[0][h] * g_vdst[(size_t)e0*192 + idx]
                      + sm_ex[1][h] * g_vdst[(size_t)e1*192 + idx]
                      + sm_ex[2][h] * g_vdst[(size_t)e2*192 + idx]
                      + sm_ex[3][h] * g_vdst[(size_t)e3*192 + idx];
                } else if (idx < 480){
                    int r2 = idx-192; int h = r2/24;
                    c = sm_ex[0][h] * g_vpts[(size_t)d0*288 + r2]
                      + sm_ex[1][h] * g_vpts[(size_t)d1*288 + r2]
                      + sm_ex[2][h] * g_vpts[(size_t)d2*288 + r2]
                      + sm_ex[3][h] * g_vpts[(size_t)d3*288 + r2];
                } else if (idx < 864){
                    int r2 = idx-480; int h = r2 >> 5; int cc = r2 & 31;
                    c = sm_ex[0][h] * g_pair[(size_t)e0*32 + cc]
                      + sm_ex[1][h] * g_pair[(size_t)e1*32 + cc]
                      + sm_ex[2][h] * g_pair[(size_t)e2*32 + cc]
                      + sm_ex[3][h] * g_pair[(size_t)e3*32 + cc];
                } else {
                    int h = idx-864;
                    c = sm_ex[0][h] + sm_ex[1][h] + sm_ex[2][h] + sm_ex[3][h];
                }
                racc[r] += c;
            }
        }
        __syncthreads();
    }
#pragma unroll
    for (int r = 0; r < 4; r++){ int idx = t + r*256; if (idx < 876) sm_acc[idx] = racc[r]; }
    __syncthreads();

    __nv_bfloat16* fh = g_fh + (size_t)n*960;
    __nv_bfloat16* fl = g_fl + (size_t)n*960;
    auto put = [&](int i, float v){
        __nv_bfloat16 h,l; split2(v,h,l); fh[i]=h; fl[i]=l;
    };
    for (int task = t; task < 672; task += 256){
        if (task < 192){
            int h = task >> 4;
            put(task, sm_acc[task] / (sm_acc[864+h] + 1e-16f));
        } else if (task < 288){
            int hp = task - 192;
            int h = hp >> 3;
            float d = sm_acc[864+h] + 1e-16f;
            float vx = sm_acc[192+hp*3+0]/d - tt[0];
            float vy = sm_acc[192+hp*3+1]/d - tt[1];
            float vz = sm_acc[192+hp*3+2]/d - tt[2];
            float lx = R[0]*vx + R[3]*vy + R[6]*vz;
            float ly = R[1]*vx + R[4]*vy + R[7]*vz;
            float lz = R[2]*vx + R[5]*vy + R[8]*vz;
            put(192+hp, lx); put(288+hp, ly); put(384+hp, lz);
            put(480+hp, sqrtf(lx*lx+ly*ly+lz*lz+1e-8f));
        } else {
            int idx = task - 288;
            int h = idx >> 5;
            put(576+idx, sm_acc[480+idx] / (sm_acc[864+h] + 1e-16f));
        }
    }
}

// ===================== host =====================
template <typename T, typename S>
static T* sym(const S& s){ void* p=nullptr; cudaGetSymbolAddress(&p, s); return (T*)p; }

extern "C" void kernel_launch(void* const* d_in, const int* in_sizes, int n_in,
                              void* d_out, int out_size)
{
    const float* s    = (const float*)d_in[0];
    const float* z    = (const float*)d_in[1];
    const int*   ei   = (const int*)d_in[2];
    const float* rots = (const float*)d_in[3];
    const float* trans= (const float*)d_in[4];
    const float* mask = (const float*)d_in[5];
    const float* Ww1  = (const float*)d_in[6];
    const float* bw1  = (const float*)d_in[7];
    const float* Ww2  = (const float*)d_in[8];
    const float* bw2  = (const float*)d_in[9];
    const float* Ww3  = (const float*)d_in[10];
    const float* bw3  = (const float*)d_in[11];
    const float* Wv1  = (const float*)d_in[12];
    const float* bv1  = (const float*)d_in[13];
    const float* Wv2  = (const float*)d_in[14];
    const float* bv2  = (const float*)d_in[15];
    const float* Wv3  = (const float*)d_in[16];
    const float* bv3  = (const float*)d_in[17];
    const float* Wq   = (const float*)d_in[18];
    const float* bq   = (const float*)d_in[19];
    const float* Wkv  = (const float*)d_in[20];
    const float* bkv  = (const float*)d_in[21];
    const float* Wb   = (const float*)d_in[22];
    const float* bb   = (const float*)d_in[23];
    const float* Wdz  = (const float*)d_in[24];
    const float* bdz  = (const float*)d_in[25];
    const float* Wo   = (const float*)d_in[26];
    const float* bo   = (const float*)d_in[27];
    const float* hw   = (const float*)d_in[28];
    float* out = (float*)d_out;

    cudaFuncSetAttribute(hmma_gemm, cudaFuncAttributeMaxDynamicSharedMemorySize, SMEM_BYTES);

    __nv_bfloat16 *zh=sym<__nv_bfloat16>(g_zh), *zl=sym<__nv_bfloat16>(g_zl);
    __nv_bfloat16 *xh=sym<__nv_bfloat16>(g_xh), *xl=sym<__nv_bfloat16>(g_xl);
    __nv_bfloat16 *yh=sym<__nv_bfloat16>(g_yh), *yl=sym<__nv_bfloat16>(g_yl);
    __nv_bfloat16 *y2h=sym<__nv_bfloat16>(g_y2h), *y2l=sym<__nv_bfloat16>(g_y2l);
    __nv_bfloat16 *fh=sym<__nv_bfloat16>(g_fh), *fl=sym<__nv_bfloat16>(g_fl);
    __nv_bfloat16 *Wnh=sym<__nv_bfloat16>(g_Wn_h),  *Wnl=sym<__nv_bfloat16>(g_Wn_l);
    __nv_bfloat16 *Wzh=sym<__nv_bfloat16>(g_Wz_h),  *Wzl=sym<__nv_bfloat16>(g_Wz_l);
    __nv_bfloat16 *W2h=sym<__nv_bfloat16>(g_Ww2_h), *W2l=sym<__nv_bfloat16>(g_Ww2_l);
    __nv_bfloat16 *V2h=sym<__nv_bfloat16>(g_Wv2_h), *V2l=sym<__nv_bfloat16>(g_Wv2_l);
    __nv_bfloat16 *V3h=sym<__nv_bfloat16>(g_Wv3_h), *V3l=sym<__nv_bfloat16>(g_Wv3_l);
    __nv_bfloat16 *Woh=sym<__nv_bfloat16>(g_Wo_h),  *Wol=sym<__nv_bfloat16>(g_Wo_l);
    float* biasN = sym<float>(g_bias_node);
    float* biasZ = sym<float>(g_bias_z);
    float* node  = sym<float>(g_node);
    float* vdst  = sym<float>(g_vdst);
    float* alog  = sym<float>(g_alog);
    float* bed   = sym<float>(g_bed);
    float* pair  = sym<float>(g_pair);

    auto tcg = [&](const __nv_bfloat16* Ah_, const __nv_bfloat16* Al_,
                   const __nv_bfloat16* Bh_, const __nv_bfloat16* Bl_,
                   const float* bias_, int M_, int K_, int Ntot_, int mode_,
                   const float* W3_,
                   float* outF_, int ldo_,
                   __nv_bfloat16* oh_, __nv_bfloat16* ol_,
                   __nv_bfloat16* o2h_, __nv_bfloat16* o2l_,
                   float* bedF_, float* pairF_){
        dim3 grid(Ntot_/96, (M_+127)/128);
        hmma_gemm<<<grid, 256, SMEM_BYTES>>>(Ah_, Al_, Bh_, Bl_, bias_, M_, K_, mode_,
                                             ei, node, W3_, outF_, ldo_, oh_, ol_,
                                             o2h_, o2l_, bedF_, pairF_);
    };

    wnconv_kernel<<<(1152*384+255)/256, 256>>>(Wq, Wkv, Ww1, Wv1);
    wzcat_kernel<<<(480*128+255)/256, 256>>>(Ww1 + 768*192, Wv1 + 384*192, Wb, Wdz);
    biascat_kernel<<<(1152+255)/256, 256>>>(bq, bkv, bw1, bv1, bb, bdz);
    splitf4_kernel<<<(unsigned)(((size_t)NE*128/4 + 255)/256), 256>>>(
        (const float4*)z, (uint2*)zh, (uint2*)zl, (size_t)NE*128/4);
    splitf4_kernel<<<(unsigned)(((size_t)NN*384/4 + 255)/256), 256>>>(
        (const float4*)s, (uint2*)fh, (uint2*)fl, (size_t)NN*384/4);

    // node projections  [NN x 1152] = s @ [Wq|Wkv|Ww1s|Ww1d|Wv1d]
    tcg(fh, fl, Wnh, Wnl, biasN, NN, 384, 1152, 0, 0, node, 1152, 0,0,0,0,0,0);
    points_kernel<<<(NN*192+255)/256, 256>>>(rots, trans);

    // remaining weight conversions
    wconv_kernel<<<(192*192+255)/256, 256>>>(Ww2, 192, 192, 192, W2h, W2l);
    wconv_kernel<<<(192*192+255)/256, 256>>>(Wv2, 192, 192, 192, V2h, V2l);
    wconv_kernel<<<(192*192+255)/256, 256>>>(Wv3, 192, 192, 192, V3h, V3l);
    wconv_kernel<<<(384*960+255)/256, 256>>>(Wo, 384, 960, 384, Woh, Wol);

    // merged z GEMM: x, y, bed, pair
    tcg(zh, zl, Wzh, Wzl, biasZ, NE, 128, 480, 6, 0, 0, 0, xh, xl, yh, yl, bed, pair);

    // init logits, then W2 GEMM with fused W3 -> atomicAdd alog
    init_logit_kernel<<<(NE*12+255)/256, 256>>>(ei, mask, hw, bw3);
    tcg(xh, xl, W2h, W2l, bw2, NE, 192, 192, 4, Ww3, alog, 0, 0,0,0,0,0,0);

    // value chain: y -> y2 -> vdst
    tcg(yh, yl, V2h, V2l, bv2, NE, 192, 192, 3, 0, 0, 0, y2h, y2l, 0,0,0,0);
    tcg(y2h, y2l, V3h, V3l, bv3, NE, 192, 192, 0, 0, vdst, 192, 0,0,0,0,0,0);

    // CSR
    zero_cnt_kernel<<<(NN+255)/256, 256>>>();
    count_kernel<<<(NE+255)/256, 256>>>(ei);
    scan_kernel<<<1, 1024>>>();
    scatter_kernel<<<(NE+255)/256, 256>>>(ei);

    // softmax + aggregation (writes split feats into fh/fl)
    aggregate_kernel<<<NN, 256>>>(ei, rots, trans);

    // output projection
    tcg(fh, fl, Woh, Wol, bo, NN, 960, 384, 0, 0, out, 384, 0,0,0,0,0,0);
}